// round 3
// baseline (speedup 1.0000x reference)
#include <cuda_runtime.h>
#include <cstdint>

// out[b,c, patch p, a, d] = x[b,c, patch (p+c)&63, a, d] + pos[c*64 + (p+c)&63]
// B=8, C=64, H=W=512, patches 8x8 of 64x64, PN=64.
//
// Pure HBM-streaming permutation+bias.
// Each thread: 8 float4 chunks at row-stride 8 within its patch column
// (identical src/dst stride = 8*128 float4). Front-batched LDG.128 x8 for
// deep MLP; streaming (.cs) loads/stores (every byte touched exactly once).

#define W4      128                   // float4 per image row
#define ROWSTEP (8 * W4)              // 1024 float4: 8 rows
#define NTHREADS_TOTAL (8u * 64u * 8u * 8u * 128u)   // 4,194,304

__global__ __launch_bounds__(256) void crosspatch_kernel(
    const float4* __restrict__ x4,
    const float*  __restrict__ pos,   // [64,64]
    float4* __restrict__ out4)
{
    unsigned idx = blockIdx.x * 256u + threadIdx.x;

    // idx = (((bc)*8 + ph)*8 + a0)*128 + w4 ; thread covers a = a0 + 8*k, k=0..7
    unsigned w4 = idx & 127u;
    unsigned t  = idx >> 7;
    unsigned a0 = t & 7u;
    unsigned t2 = t >> 3;
    unsigned ph = t2 & 7u;
    unsigned bc = t2 >> 3;           // b*64 + c
    unsigned c  = bc & 63u;

    unsigned pw = w4 >> 4;           // dest patch col
    unsigned p  = (ph << 3) | pw;    // dest patch id
    unsigned sp = (p + c) & 63u;     // source patch id
    unsigned sph = sp >> 3;
    unsigned spw = sp & 7u;

    unsigned dst = ((bc << 9) + (ph  << 6) + a0) * 128u + w4;
    unsigned src = ((bc << 9) + (sph << 6) + a0) * 128u + (spw << 4) + (w4 & 15u);

    float bias = __ldg(&pos[(c << 6) + sp]);

    float4 v[8];
#pragma unroll
    for (int k = 0; k < 8; k++)
        v[k] = __ldcs(&x4[src + (unsigned)k * ROWSTEP]);

#pragma unroll
    for (int k = 0; k < 8; k++) {
        v[k].x += bias; v[k].y += bias; v[k].z += bias; v[k].w += bias;
    }

#pragma unroll
    for (int k = 0; k < 8; k++)
        __stcs(&out4[dst + (unsigned)k * ROWSTEP], v[k]);
}

extern "C" void kernel_launch(void* const* d_in, const int* in_sizes, int n_in,
                              void* d_out, int out_size)
{
    const float4* x4  = (const float4*)d_in[0];
    const float*  pos = (const float*)d_in[1];
    float4* out4 = (float4*)d_out;

    unsigned blocks = NTHREADS_TOTAL / 256u;   // 16384
    crosspatch_kernel<<<blocks, 256>>>(x4, pos, out4);
}